// round 13
// baseline (speedup 1.0000x reference)
#include <cuda_runtime.h>
#include <cuda_fp16.h>
#include <cstdint>

#define BATCH 4096
#define D 256
#define N2 8192
#define NBLK 2080     // 64*65/2 triangular 128x128 tiles
#define GRID 148      // 1 CTA/SM, 512 threads, 2 warp-groups
#define NGROUPS 296
#define NIT 8         // ceil(2080/296); fixed rounds for symmetric handshakes

// ---------------- device scratch (zero-init at load; kernel restores before exit) ----------------
__device__ double   g_colsum[D];
__device__ double   g_sum_sq;
__device__ float    g_sq[N2];
__device__ float    g_g0;
__device__ double   g_disc;
__device__ unsigned g_cnt_pro;
__device__ unsigned g_cnt_mma;
__device__ unsigned g_conv;    // conversion done -> mainloop may start
__device__ unsigned g_ready;   // g0 available  -> epilogue may run
__device__ __align__(16) __half g_half[(size_t)N2 * D];

__device__ __forceinline__ uint32_t smem_u32(const void* p) {
    uint32_t a;
    asm("{ .reg .u64 t; cvta.to.shared.u64 t, %1; cvt.u32.u64 %0, t; }" : "=r"(a) : "l"(p));
    return a;
}
#define CP_ASYNC16(dst, src) asm volatile("cp.async.ca.shared.global [%0], [%1], 16;" :: "r"(dst), "l"(src))
#define CP_COMMIT()          asm volatile("cp.async.commit_group;" ::: "memory")
#define CP_WAIT(n)           asm volatile("cp.async.wait_group %0;" :: "n"(n) : "memory")
#define BAR_SYNC(id, cnt)    asm volatile("bar.sync %0, %1;"   :: "r"(id), "r"(cnt) : "memory")
#define BAR_ARRIVE(id, cnt)  asm volatile("bar.arrive %0, %1;" :: "r"(id), "r"(cnt) : "memory")

// arg <= 0; 5-kernel sum e + e^2 + e^4 + e^8 + e^16 via one MUFU EX2
__device__ __forceinline__ float kern5e(float arg) {
    float e;
    asm("ex2.approx.ftz.f32 %0, %1;" : "=f"(e) : "f"(fminf(arg, 0.f)));
    float e2 = e * e, e4 = e2 * e2, e8 = e4 * e4;
    return e + e2 + e4 + e8 + e8 * e8;
}

__device__ __forceinline__ void tri_coords(int x, int& bi, int& bj) {
    bi = (int)((sqrtf(8.f * x + 1.f) - 1.f) * 0.5f);
    while ((bi + 1) * (bi + 2) / 2 <= x) bi++;
    while (bi * (bi + 1) / 2 > x) bi--;
    bj = x - bi * (bi + 1) / 2;
}

// per-group smem: A dbl-buf 32K, B dbl-buf 32K, sqj 512B, red 32B
#define GSM_A     0
#define GSM_B     32768
#define GSM_SQJ   65536
#define GSM_RED   66048
#define GROUP_BYTES 66560          // 65*1024, keeps group-1 base 1024-aligned
#define SMEM_TOTAL (2 * GROUP_BYTES)

__global__ void __launch_bounds__(512, 1) mmd_fused(const float* __restrict__ S,
                                                    const float* __restrict__ T,
                                                    float* __restrict__ out) {
    extern __shared__ __align__(1024) uint8_t dsm[];
    const int tid = threadIdx.x;
    const int wid = tid >> 5, lane = tid & 31;
    __shared__ unsigned s_flag;

    // ================= Phase A: prologue (all 148 CTAs, 512 threads) =================
    {
        float* cs = (float*)dsm;                // 256 colsum partials
        float* ss = (float*)(dsm + 1024);       // 16 per-warp sumsq partials
        if (tid < 256) cs[tid] = 0.f;
        if (tid < 16)  ss[tid] = 0.f;
        __syncthreads();
        float cp[8] = {0.f, 0.f, 0.f, 0.f, 0.f, 0.f, 0.f, 0.f};
        float sqacc = 0.f;
        for (int row = blockIdx.x * 16 + wid; row < N2; row += GRID * 16) {
            const float* F = (row < BATCH) ? (S + (size_t)row * D) : (T + (size_t)(row - BATCH) * D);
            float4 a = ((const float4*)F)[lane];
            float4 b = ((const float4*)F)[lane + 32];
            cp[0] += a.x; cp[1] += a.y; cp[2] += a.z; cp[3] += a.w;
            cp[4] += b.x; cp[5] += b.y; cp[6] += b.z; cp[7] += b.w;
            float s = a.x*a.x + a.y*a.y + a.z*a.z + a.w*a.w
                    + b.x*b.x + b.y*b.y + b.z*b.z + b.w*b.w;
            __half2* H = (__half2*)(g_half + (size_t)row * D);
            H[lane * 2 + 0]      = __floats2half2_rn(a.x, a.y);
            H[lane * 2 + 1]      = __floats2half2_rn(a.z, a.w);
            H[64 + lane * 2 + 0] = __floats2half2_rn(b.x, b.y);
            H[64 + lane * 2 + 1] = __floats2half2_rn(b.z, b.w);
            #pragma unroll
            for (int off = 16; off > 0; off >>= 1) s += __shfl_down_sync(0xffffffffu, s, off);
            if (lane == 0) { g_sq[row] = s; sqacc += s; }
        }
        #pragma unroll
        for (int q = 0; q < 4; ++q) atomicAdd(&cs[4 * lane + q], cp[q]);
        #pragma unroll
        for (int q = 0; q < 4; ++q) atomicAdd(&cs[128 + 4 * lane + q], cp[4 + q]);
        if (lane == 0) atomicAdd(&ss[wid], sqacc);
        __syncthreads();
        if (tid < 256) atomicAdd(&g_colsum[tid], (double)cs[tid]);
        if (tid == 0) {
            float s16 = 0.f;
            #pragma unroll
            for (int i = 0; i < 16; ++i) s16 += ss[i];
            atomicAdd(&g_sum_sq, (double)s16);
        }
        __threadfence();
        if (tid == 0) s_flag = (atomicAdd(&g_cnt_pro, 1u) == GRID - 1) ? 1u : 0u;
        __syncthreads();
        if (s_flag) {
            if (tid == 0) atomicExch(&g_conv, 1u);   // release mainloops FIRST
            double* rc = (double*)dsm;               // 2KB
            if (tid < 256) {
                double v = g_colsum[tid];
                rc[tid] = v * v;
                g_colsum[tid] = 0.0;                 // restore for next replay
            }
            __syncthreads();
            for (int k = 128; k > 0; k >>= 1) {
                if (tid < k) rc[tid] += rc[tid + k];
                __syncthreads();
            }
            if (tid == 0) {
                double sum_dist = 2.0 * (double)N2 * g_sum_sq - 2.0 * rc[0];
                double bandwidth = ((double)N2 * (double)N2 - (double)N2) / sum_dist;
                g_g0 = (float)(bandwidth / 4.0);     // / 2^(NUM_KERNELS//2)
                g_sum_sq = 0.0;
                g_cnt_pro = 0;
                __threadfence();
                atomicExch(&g_ready, 1u);
            }
        }
    }
    if (tid == 0) {
        while (atomicAdd(&g_conv, 0u) == 0u) __nanosleep(32);
    }
    __syncthreads();
    // ===== from here on: NO __syncthreads until both groups finish (named barriers only) =====

    // ================= Phase B: two warp-groups, ping-pong tensor token =================
    const int g  = tid >> 8;          // warp-group 0 / 1
    const int gt = tid & 255;
    const int gwid = gt >> 5;
    const int wm = gwid & 3, wn = gwid >> 2;
    const int gq = lane >> 2, j4 = lane & 3;
    uint8_t* gsm = dsm + (uint32_t)g * GROUP_BYTES;
    float* sqj = (float*)(gsm + GSM_SQJ);
    float* red = (float*)(gsm + GSM_RED);
    const uint32_t sb = smem_u32(gsm);
    const int GBAR = 1 + g;           // intra-group barrier id
    const int TOK_WAIT = 3 + g;       // g0 waits on 3, g1 waits on 4
    const int TOK_PASS = 4 - g;       // g0 arrives 4, g1 arrives 3

    uint32_t aoff[2], boff[4];
    {
        int rA = wm * 32 + (lane & 15);
        int ca = (lane >> 4) * 16;
        #pragma unroll
        for (int mi = 0; mi < 2; ++mi) {
            uint32_t b0 = (uint32_t)((rA + mi * 16) * 128 + ca);
            aoff[mi] = b0 ^ ((b0 >> 3) & 0x70);
        }
        int rB = wn * 64 + (lane & 7) + ((lane >= 16) ? 8 : 0);
        int cb = (((lane >> 3) & 1) ? 16 : 0);
        #pragma unroll
        for (int nj = 0; nj < 4; ++nj) {
            uint32_t b0 = (uint32_t)((rB + nj * 16) * 128 + cb);
            boff[nj] = b0 ^ ((b0 >> 3) & 0x70);
        }
    }
    uint32_t stoff[4];
    #pragma unroll
    for (int r = 0; r < 4; ++r) {
        uint32_t b0 = (uint32_t)(((gt >> 3) + r * 32) * 128 + (gt & 7) * 16);
        stoff[r] = b0 ^ ((b0 >> 3) & 0x70);
    }
    const int ldrow = gt >> 3, ldf4 = gt & 7;

    float ngv = 0.f, m2ngv = 0.f;
    bool have_ng = false;
    double dacc = 0.0;

    int x = blockIdx.x * 2 + g;       // group id in [0, 296)
    int bi, bj;
    tri_coords(x, bi, bj);
    int i0 = bi * 128, j0 = bj * 128;

    {   // prefetch chunk 0 of first tile (after conversion barrier)
        const __half* pa = g_half + (size_t)(i0 + ldrow) * D + ldf4 * 8;
        const __half* pb = g_half + (size_t)(j0 + ldrow) * D + ldf4 * 8;
        #pragma unroll
        for (int r = 0; r < 4; ++r) {
            CP_ASYNC16(sb + GSM_A + stoff[r], pa + (size_t)r * 32 * D);
            CP_ASYNC16(sb + GSM_B + stoff[r], pb + (size_t)r * 32 * D);
        }
        CP_COMMIT();
    }

    for (int k = 0; k < NIT; ++k) {
        const bool valid = (x < NBLK);
        int xn = x + NGROUPS;
        const bool hasnext = xn < NBLK;
        int i0n = 0, j0n = 0;
        if (hasnext) {
            int bin, bjn;
            tri_coords(xn, bin, bjn);
            i0n = bin * 128; j0n = bjn * 128;
        }

        float acc[2][8][4];
        #pragma unroll
        for (int mi = 0; mi < 2; ++mi)
            #pragma unroll
            for (int ni = 0; ni < 8; ++ni)
                #pragma unroll
                for (int q = 0; q < 4; ++q) acc[mi][ni][q] = 0.f;

        // ---- wait for the tensor token (group 0 owns it initially) ----
        if (!(g == 0 && k == 0)) BAR_SYNC(TOK_WAIT, 512);

        if (valid) {
            #pragma unroll
            for (int c = 0; c < 4; ++c) {
                CP_WAIT(0);
                BAR_SYNC(GBAR, 256);
                if (c == 0 && gt < 128) sqj[gt] = g_sq[j0 + gt];
                {   // prefetch one chunk ahead into the just-drained buffer
                    int pi = i0, pj = j0, kc = (c + 1) * 64;
                    bool doit = true;
                    if (c == 3) { pi = i0n; pj = j0n; kc = 0; doit = hasnext; }
                    if (doit) {
                        const uint32_t nbA = sb + GSM_A + ((c + 1) & 1) * 16384;
                        const uint32_t nbB = sb + GSM_B + ((c + 1) & 1) * 16384;
                        const __half* pa = g_half + (size_t)(pi + ldrow) * D + kc + ldf4 * 8;
                        const __half* pb = g_half + (size_t)(pj + ldrow) * D + kc + ldf4 * 8;
                        #pragma unroll
                        for (int r = 0; r < 4; ++r) {
                            CP_ASYNC16(nbA + stoff[r], pa + (size_t)r * 32 * D);
                            CP_ASYNC16(nbB + stoff[r], pb + (size_t)r * 32 * D);
                        }
                    }
                    CP_COMMIT();   // exactly one group per chunk (may be empty)
                }
                const uint32_t bufA = sb + GSM_A + (c & 1) * 16384;
                const uint32_t bufB = sb + GSM_B + (c & 1) * 16384;
                #pragma unroll
                for (int ks = 0; ks < 4; ++ks) {
                    uint32_t a[2][4], b[4][4];
                    #pragma unroll
                    for (int mi = 0; mi < 2; ++mi)
                        asm volatile("ldmatrix.sync.aligned.m8n8.x4.shared.b16 {%0,%1,%2,%3}, [%4];"
                            : "=r"(a[mi][0]), "=r"(a[mi][1]), "=r"(a[mi][2]), "=r"(a[mi][3])
                            : "r"(bufA + (aoff[mi] ^ (ks * 32))));
                    #pragma unroll
                    for (int nj = 0; nj < 4; ++nj)
                        asm volatile("ldmatrix.sync.aligned.m8n8.x4.shared.b16 {%0,%1,%2,%3}, [%4];"
                            : "=r"(b[nj][0]), "=r"(b[nj][1]), "=r"(b[nj][2]), "=r"(b[nj][3])
                            : "r"(bufB + (boff[nj] ^ (ks * 32))));
                    #pragma unroll
                    for (int mi = 0; mi < 2; ++mi)
                        #pragma unroll
                        for (int ni = 0; ni < 8; ++ni) {
                            uint32_t b0 = b[ni >> 1][(ni & 1) * 2];
                            uint32_t b1 = b[ni >> 1][(ni & 1) * 2 + 1];
                            asm volatile(
                                "mma.sync.aligned.m16n8k16.row.col.f32.f16.f16.f32 "
                                "{%0,%1,%2,%3}, {%4,%5,%6,%7}, {%8,%9}, {%0,%1,%2,%3};"
                                : "+f"(acc[mi][ni][0]), "+f"(acc[mi][ni][1]),
                                  "+f"(acc[mi][ni][2]), "+f"(acc[mi][ni][3])
                                : "r"(a[mi][0]), "r"(a[mi][1]), "r"(a[mi][2]), "r"(a[mi][3]),
                                  "r"(b0), "r"(b1));
                        }
                }
            }
        }

        // ---- pass the token: partner's MMA phase overlaps our epilogue ----
        BAR_ARRIVE(TOK_PASS, 512);

        if (valid) {
            if (!have_ng) {   // first epilogue only; g0 long since computed
                if (gt == 0) {
                    while (atomicAdd(&g_ready, 0u) == 0u) __nanosleep(32);
                }
                BAR_SYNC(GBAR, 256);
                ngv = -g_g0 * 1.44269504088896340736f;
                m2ngv = -2.f * ngv;
                have_ng = true;
            }
            float sing[2][2];
            #pragma unroll
            for (int mi = 0; mi < 2; ++mi) {
                sing[mi][0] = g_sq[i0 + wm * 32 + mi * 16 + gq] * ngv;
                sing[mi][1] = g_sq[i0 + wm * 32 + mi * 16 + gq + 8] * ngv;
            }
            float accsum = 0.f;
            #pragma unroll
            for (int mi = 0; mi < 2; ++mi)
                #pragma unroll
                for (int ni = 0; ni < 8; ++ni) {
                    int cb = wn * 64 + ni * 8 + 2 * j4;
                    float sj0 = sqj[cb], sj1 = sqj[cb + 1];
                    float a0 = fmaf(sj0, ngv, sing[mi][0]);
                    float a1 = fmaf(sj1, ngv, sing[mi][0]);
                    float a2 = fmaf(sj0, ngv, sing[mi][1]);
                    float a3 = fmaf(sj1, ngv, sing[mi][1]);
                    accsum += kern5e(fmaf(acc[mi][ni][0], m2ngv, a0))
                            + kern5e(fmaf(acc[mi][ni][1], m2ngv, a1))
                            + kern5e(fmaf(acc[mi][ni][2], m2ngv, a2))
                            + kern5e(fmaf(acc[mi][ni][3], m2ngv, a3));
                }
            float w = (((i0 < BATCH) == (j0 < BATCH)) ? 1.f : -1.f) * ((bi == bj) ? 1.f : 2.f);
            accsum *= w;
            #pragma unroll
            for (int off = 16; off > 0; off >>= 1)
                accsum += __shfl_down_sync(0xffffffffu, accsum, off);
            if (lane == 0) red[gwid] = accsum;
            BAR_SYNC(GBAR, 256);
            if (gt == 0) {
                float s = 0.f;
                #pragma unroll
                for (int i = 0; i < 8; ++i) s += red[i];
                dacc += (double)s;
            }
            // next MMA phase's GBAR orders red/sqj reuse
        }

        x = xn;
        if (hasnext) { bi = i0n >> 7; bj = j0n >> 7; i0 = i0n; j0 = j0n; }
    }

    if (gt == 0) { atomicAdd(&g_disc, dacc); __threadfence(); }
    __syncthreads();   // both groups completed fixed NIT rounds

    // ---- last CTA writes the output and restores state for graph replay ----
    if (tid == 0) s_flag = (atomicAdd(&g_cnt_mma, 1u) == GRID - 1) ? 1u : 0u;
    __syncthreads();
    if (s_flag && tid == 0) {
        double dsum = atomicAdd(&g_disc, 0.0);   // L2-coherent read
        out[0] = (float)(dsum / (5.0 * (double)BATCH * (double)BATCH));
        g_disc = 0.0;
        g_cnt_mma = 0;
        atomicExch(&g_conv, 0u);
        atomicExch(&g_ready, 0u);
    }
}

extern "C" void kernel_launch(void* const* d_in, const int* in_sizes, int n_in,
                              void* d_out, int out_size) {
    const float* S = (const float*)d_in[0];
    const float* T = (const float*)d_in[1];
    cudaFuncSetAttribute(mmd_fused, cudaFuncAttributeMaxDynamicSharedMemorySize, SMEM_TOTAL);
    mmd_fused<<<GRID, 512, SMEM_TOTAL>>>(S, T, (float*)d_out);
}